// round 7
// baseline (speedup 1.0000x reference)
#include <cuda_runtime.h>
#include <cuda_bf16.h>
#include <cstdint>
#include <cstddef>

#define BATCH 64
#define SEQ   512
#define DIM   512
#define HID   256
#define NK    32

typedef unsigned long long u64;

// ---------------- scratch (__device__ globals; no allocation) ----------------
// xp layout: [t*64+b][g]  ((t*64+b)*2048 + g)
__device__ float g_xp[(size_t)SEQ * BATCH * 2048];          // 256 MiB
__device__ float g_hout[(size_t)2 * SEQ * HID * BATCH];     // 64 MiB:  [dir][t][j][b]
__device__ float g_hbuf[2 * 2 * HID * BATCH];               // [dir][buf][k][b]
__device__ __nv_bfloat16 g_xhi[(size_t)32768 * 512];
__device__ __nv_bfloat16 g_xlo[(size_t)32768 * 512];
__device__ __nv_bfloat16 g_whi[(size_t)2048 * 512];
__device__ __nv_bfloat16 g_wlo[(size_t)2048 * 512];
__device__ unsigned g_bar_count = 0;
__device__ unsigned g_bar_phase = 0;

// ---------------- mma.sync / ldmatrix / cp.async helpers ----------------
__device__ __forceinline__ uint32_t smem_to_u32(const void* p) {
    uint32_t a;
    asm("{ .reg .u64 t; cvta.to.shared.u64 t, %1; cvt.u32.u64 %0, t; }" : "=r"(a) : "l"(p));
    return a;
}
__device__ __forceinline__ void cp_async16(uint32_t saddr, const void* gptr) {
    asm volatile("cp.async.cg.shared.global [%0], [%1], 16;" :: "r"(saddr), "l"(gptr));
}
#define CP_COMMIT() asm volatile("cp.async.commit_group;")
#define CP_WAIT(n)  asm volatile("cp.async.wait_group %0;" :: "n"(n) : "memory")

__device__ __forceinline__ void ldsm4(uint32_t* r, uint32_t addr) {
    asm volatile("ldmatrix.sync.aligned.m8n8.x4.shared.b16 {%0,%1,%2,%3}, [%4];"
        : "=r"(r[0]), "=r"(r[1]), "=r"(r[2]), "=r"(r[3]) : "r"(addr));
}
__device__ __forceinline__ void mma16816(float* c, const uint32_t* a, uint32_t b0, uint32_t b1) {
    asm volatile("mma.sync.aligned.m16n8k16.row.col.f32.bf16.bf16.f32 "
        "{%0,%1,%2,%3}, {%4,%5,%6,%7}, {%8,%9}, {%0,%1,%2,%3};"
        : "+f"(c[0]), "+f"(c[1]), "+f"(c[2]), "+f"(c[3])
        : "r"(a[0]), "r"(a[1]), "r"(a[2]), "r"(a[3]), "r"(b0), "r"(b1));
}

// ---------------- grid barrier (all 128 CTAs co-resident; R4-proven) --------
__device__ __forceinline__ void grid_barrier(unsigned nb)
{
    __threadfence();
    __syncthreads();
    if (threadIdx.x == 0) {
        volatile unsigned* vph = &g_bar_phase;
        unsigned ph = *vph;
        unsigned old = atomicAdd(&g_bar_count, 1u);
        if (old == nb - 1u) {
            atomicExch(&g_bar_count, 0u);
            __threadfence();
            atomicAdd(&g_bar_phase, 1u);
        } else {
            while (*vph == ph) { __nanosleep(64); }
        }
    }
    __syncthreads();
}

// ---------------- Kernel 0: fp32 -> bf16 hi/lo split ----------------
__global__ __launch_bounds__(256) void split_kernel(
    const float* __restrict__ src, __nv_bfloat16* __restrict__ hi,
    __nv_bfloat16* __restrict__ lo, int n)
{
    int stride = gridDim.x * blockDim.x;
    for (int i = blockIdx.x * blockDim.x + threadIdx.x; i < n; i += stride) {
        float v = src[i];
        __nv_bfloat16 h = __float2bfloat16(v);
        float hv = __bfloat162float(h);
        __nv_bfloat16 l = __float2bfloat16(v - hv);
        hi[i] = h; lo[i] = l;
    }
}

// ---------------- Kernel 1: bf16 3-split GEMM via mma.sync ----------------
#define NCHUNK 32
__global__ __launch_bounds__(256) void gemm_xp_mma_kernel(
    const float* __restrict__ bf_, const float* __restrict__ bb_)
{
    __shared__ __align__(128) char sm[2][16384];
    __shared__ float s_bias[128];

    const int tid  = threadIdx.x;
    const int lane = tid & 31;
    const int wid  = tid >> 5;
    const int wm   = wid >> 2;
    const int wn   = wid & 3;
    const int nTile = blockIdx.x;
    const int mTile = blockIdx.y;
    const int mBase = mTile * 128;
    const int nBase = nTile * 128;

    if (tid < 128) {
        const float* bsrc = (nTile < 8) ? bf_ : bb_;
        int boff = (nTile < 8) ? nTile * 128 : (nTile - 8) * 128;
        s_bias[tid] = bsrc[boff + tid];
    }

    const uint32_t smem_base = smem_to_u32(sm);

    uint32_t aoff[2][4];
    {
        const int arow = wm * 64 + (lane & 15);
        const int akc  = lane >> 4;
#pragma unroll
        for (int mf = 0; mf < 4; mf++) {
            const int r = arow + mf * 16;
            const uint32_t o = (uint32_t)(r * 32 + ((akc ^ ((r >> 2) & 1)) << 4));
            aoff[0][mf] = o;
            aoff[1][mf] = o + 4096u;
        }
    }
    uint32_t boff[2][2];
    {
        const int nrow = wn * 32 + (lane & 7) + ((lane >> 4) << 3);
        const int bkc  = (lane >> 3) & 1;
#pragma unroll
        for (int p = 0; p < 2; p++) {
            const int r = nrow + p * 16;
            const uint32_t o = (uint32_t)(r * 32 + ((bkc ^ ((r >> 2) & 1)) << 4));
            boff[0][p] = o + 8192u;
            boff[1][p] = o + 12288u;
        }
    }

    const int ldrow = tid >> 1;
    const int ldck  = tid & 1;
    const uint32_t ld_soff = (uint32_t)(ldrow * 32 + ((ldck ^ ((ldrow >> 2) & 1)) << 4));
    const __nv_bfloat16* Ahg = g_xhi + (size_t)(mBase + ldrow) * 512 + ldck * 8;
    const __nv_bfloat16* Alg = g_xlo + (size_t)(mBase + ldrow) * 512 + ldck * 8;
    const __nv_bfloat16* Bhg = g_whi + (size_t)(nBase + ldrow) * 512 + ldck * 8;
    const __nv_bfloat16* Blg = g_wlo + (size_t)(nBase + ldrow) * 512 + ldck * 8;

    float cr[4][4][4];
#pragma unroll
    for (int mf = 0; mf < 4; mf++)
#pragma unroll
        for (int nf = 0; nf < 4; nf++)
#pragma unroll
            for (int q = 0; q < 4; q++) cr[mf][nf][q] = 0.f;

    {
        const uint32_t so = smem_base + ld_soff;
        cp_async16(so,          Ahg);
        cp_async16(so + 4096u,  Alg);
        cp_async16(so + 8192u,  Bhg);
        cp_async16(so + 12288u, Blg);
        CP_COMMIT();
    }

    for (int c = 0; c < NCHUNK; c++) {
        if (c + 1 < NCHUNK) {
            const int kb = (c + 1) * 16;
            const uint32_t so = smem_base + ((c + 1) & 1) * 16384u + ld_soff;
            cp_async16(so,          Ahg + kb);
            cp_async16(so + 4096u,  Alg + kb);
            cp_async16(so + 8192u,  Bhg + kb);
            cp_async16(so + 12288u, Blg + kb);
            CP_COMMIT();
            CP_WAIT(1);
        } else {
            CP_WAIT(0);
        }
        __syncthreads();

        const uint32_t stg = smem_base + (c & 1) * 16384u;

        uint32_t ah[4][4];
#pragma unroll
        for (int mf = 0; mf < 4; mf++) ldsm4(ah[mf], stg + aoff[0][mf]);
        uint32_t bh[2][4];
#pragma unroll
        for (int p = 0; p < 2; p++) ldsm4(bh[p], stg + boff[0][p]);
#pragma unroll
        for (int mf = 0; mf < 4; mf++)
#pragma unroll
            for (int nf = 0; nf < 4; nf++)
                mma16816(cr[mf][nf], ah[mf], bh[nf >> 1][2 * (nf & 1)], bh[nf >> 1][2 * (nf & 1) + 1]);

        uint32_t bl[2][4];
#pragma unroll
        for (int p = 0; p < 2; p++) ldsm4(bl[p], stg + boff[1][p]);
#pragma unroll
        for (int mf = 0; mf < 4; mf++)
#pragma unroll
            for (int nf = 0; nf < 4; nf++)
                mma16816(cr[mf][nf], ah[mf], bl[nf >> 1][2 * (nf & 1)], bl[nf >> 1][2 * (nf & 1) + 1]);

        uint32_t al[4][4];
#pragma unroll
        for (int mf = 0; mf < 4; mf++) ldsm4(al[mf], stg + aoff[1][mf]);
#pragma unroll
        for (int mf = 0; mf < 4; mf++)
#pragma unroll
            for (int nf = 0; nf < 4; nf++)
                mma16816(cr[mf][nf], al[mf], bh[nf >> 1][2 * (nf & 1)], bh[nf >> 1][2 * (nf & 1) + 1]);

        __syncthreads();
    }

#pragma unroll
    for (int mf = 0; mf < 4; mf++) {
        const int m0 = mBase + wm * 64 + mf * 16 + (lane >> 2);
        const int m1 = m0 + 8;
        const size_t r0 = ((size_t)(m0 & 511) * 64 + (m0 >> 9)) * 2048;
        const size_t r1 = ((size_t)(m1 & 511) * 64 + (m1 >> 9)) * 2048;
#pragma unroll
        for (int nf = 0; nf < 4; nf++) {
            const int nl = wn * 32 + nf * 8 + (lane & 3) * 2;
            const float b0 = s_bias[nl], b1 = s_bias[nl + 1];
            const int n = nBase + nl;
            float2 v0 = make_float2(cr[mf][nf][0] + b0, cr[mf][nf][1] + b1);
            float2 v1 = make_float2(cr[mf][nf][2] + b0, cr[mf][nf][3] + b1);
            *(float2*)&g_xp[r0 + n] = v0;
            *(float2*)&g_xp[r1 + n] = v1;
        }
    }
}

// ---------------- Kernel 2: persistent biLSTM recurrence (256 threads) ------
// 128 CTAs (64/dir). CTA (dir,s) owns h-indices [4s,4s+4) = 16 gate rows.
// Warp w owns rows {2w,2w+1}; lane L owns batches {2L,2L+1}.
__global__ __launch_bounds__(256) void lstm_kernel(
    const float* __restrict__ Whh_f, const float* __restrict__ Whh_b,
    const int* __restrict__ lengths)
{
    __shared__ __align__(16) float Wsm[16 * 264];      // 16.9 KB
    __shared__ __align__(16) float hsm[2][2048];       // 16 KB (2 x 32k-rows x 64b)
    __shared__ __align__(16) float xsm[16 * 64];       // 4 KB
    __shared__ float gsm[16 * 64];                     // 4 KB
    __shared__ float csm[4 * 64];                      // 1 KB
    __shared__ float hpv[4 * 64];                      // 1 KB
    __shared__ int   len_sm[64];

    const int tid = threadIdx.x;
    const int cta = blockIdx.x;
    const int dir = cta >> 6;
    const int s   = cta & 63;
    const int s4  = s * 4;
    const float* Whh = dir ? Whh_b : Whh_f;

    for (int idx = tid; idx < 16 * 256; idx += 256) {
        int ri = idx >> 8, k = idx & 255;
        int q = ri >> 2, j = ri & 3;
        Wsm[ri * 264 + k] = Whh[(q * 256 + s4 + j) * 256 + k];
    }
    if (tid < 64) len_sm[tid] = lengths[tid];
    csm[tid] = 0.f;
    hpv[tid] = 0.f;

    {   // zero my rows of hbuf[dir][0]
        float* hb0 = g_hbuf + (dir * 2 + 0) * HID * BATCH;
        int j = tid >> 6, b = tid & 63;
        hb0[(s4 + j) * 64 + b] = 0.f;
    }
    grid_barrier(gridDim.x);

    const int w    = tid >> 5;       // 0..7
    const int lane = tid & 31;
    const int ri0 = 2 * w, ri1 = 2 * w + 1;
    const int b2  = 2 * lane;
    const int aj  = tid >> 6;        // activation j (0..3)
    const int ab  = tid & 63;        // activation b
    const int xq  = tid >> 6;        // xp stage quadrant
    const int xb  = tid & 63;        // xp stage batch

    for (int st = 0; st < SEQ; st++) {
        const int tstep = dir ? (SEQ - 1 - st) : st;
        const int gbuf  = st & 1;
        const float* hgl  = g_hbuf + (dir * 2 + gbuf) * HID * BATCH;
        float*       hgln = g_hbuf + (dir * 2 + (gbuf ^ 1)) * HID * BATCH;

        // stage xp: 256 threads x 1 float4 = (16 rows x 64 b)
        {
            float4 xv = __ldg((const float4*)&g_xp[((size_t)tstep * 64 + xb) * 2048
                                                   + dir * 1024 + xq * 256 + s4]);
            xsm[(xq * 4 + 0) * 64 + xb] = xv.x;
            xsm[(xq * 4 + 1) * 64 + xb] = xv.y;
            xsm[(xq * 4 + 2) * 64 + xb] = xv.z;
            xsm[(xq * 4 + 3) * 64 + xb] = xv.w;
        }

        // prefetch h chunk 0 (2 float4/thread)
        float4 pf0 = __ldcg(((const float4*)hgl) + tid);
        float4 pf1 = __ldcg(((const float4*)hgl) + tid + 256);
        ((float4*)hsm[0])[tid]       = pf0;
        ((float4*)hsm[0])[tid + 256] = pf1;
        __syncthreads();

        float acc[2][2];
        {
            float2 x0 = *(const float2*)&xsm[ri0 * 64 + b2];
            float2 x1 = *(const float2*)&xsm[ri1 * 64 + b2];
            acc[0][0] = x0.x; acc[0][1] = x0.y;
            acc[1][0] = x1.x; acc[1][1] = x1.y;
        }

        for (int cc = 0; cc < 8; cc++) {
            const int cb = cc & 1;
            if (cc < 7) {
                pf0 = __ldcg(((const float4*)hgl) + (cc + 1) * 512 + tid);
                pf1 = __ldcg(((const float4*)hgl) + (cc + 1) * 512 + tid + 256);
            }
            const float* hrow = hsm[cb];
            const float* w0p = &Wsm[ri0 * 264 + cc * 32];
            const float* w1p = &Wsm[ri1 * 264 + cc * 32];
#pragma unroll
            for (int kk = 0; kk < 32; kk += 4) {
                float4 w0 = *(const float4*)&w0p[kk];
                float4 w1 = *(const float4*)&w1p[kk];
                float2 h0 = *(const float2*)&hrow[(kk + 0) * 64 + b2];
                float2 h1 = *(const float2*)&hrow[(kk + 1) * 64 + b2];
                float2 h2 = *(const float2*)&hrow[(kk + 2) * 64 + b2];
                float2 h3 = *(const float2*)&hrow[(kk + 3) * 64 + b2];
                acc[0][0] += w0.x * h0.x; acc[0][1] += w0.x * h0.y;
                acc[1][0] += w1.x * h0.x; acc[1][1] += w1.x * h0.y;
                acc[0][0] += w0.y * h1.x; acc[0][1] += w0.y * h1.y;
                acc[1][0] += w1.y * h1.x; acc[1][1] += w1.y * h1.y;
                acc[0][0] += w0.z * h2.x; acc[0][1] += w0.z * h2.y;
                acc[1][0] += w1.z * h2.x; acc[1][1] += w1.z * h2.y;
                acc[0][0] += w0.w * h3.x; acc[0][1] += w0.w * h3.y;
                acc[1][0] += w1.w * h3.x; acc[1][1] += w1.w * h3.y;
            }
            if (cc < 7) {
                __syncthreads();
                ((float4*)hsm[cb ^ 1])[tid]       = pf0;
                ((float4*)hsm[cb ^ 1])[tid + 256] = pf1;
                __syncthreads();
            }
        }

        *(float2*)&gsm[ri0 * 64 + b2] = make_float2(acc[0][0], acc[0][1]);
        *(float2*)&gsm[ri1 * 64 + b2] = make_float2(acc[1][0], acc[1][1]);
        __syncthreads();

        {
            const int j = aj, b = ab;
            float gi = gsm[(0 * 4 + j) * 64 + b];
            float gf = gsm[(1 * 4 + j) * 64 + b];
            float gg = gsm[(2 * 4 + j) * 64 + b];
            float go = gsm[(3 * 4 + j) * 64 + b];
            float i_ = 1.f / (1.f + expf(-gi));
            float f_ = 1.f / (1.f + expf(-gf));
            float o_ = 1.f / (1.f + expf(-go));
            float g_ = tanhf(gg);
            float c_old = csm[j * 64 + b];
            float h_old = hpv[j * 64 + b];
            float c_new = f_ * c_old + i_ * g_;
            float h_new = o_ * tanhf(c_new);
            bool  m = (tstep < len_sm[b]);
            float c_out = m ? c_new : c_old;
            float h_out = m ? h_new : h_old;
            csm[j * 64 + b] = c_out;
            hpv[j * 64 + b] = h_out;
            __stcg(&hgln[(s4 + j) * 64 + b], h_out);
            g_hout[((size_t)(dir * SEQ + tstep) * HID + (s4 + j)) * 64 + b] = h_out;
        }
        grid_barrier(gridDim.x);
    }
}

// ---------------- Kernel 3: logits = [h_f;h_b] @ W_clf^T + b_clf ----------------
__global__ __launch_bounds__(256) void clf_kernel(
    const float* __restrict__ Wclf, const float* __restrict__ bclf,
    float* __restrict__ out)
{
    __shared__ float Ws[32 * 65];
    __shared__ __align__(16) float hs[64 * 64];
    const int t   = blockIdx.x;
    const int tid = threadIdx.x;
    const int n   = tid & 31;
    const int bg  = tid >> 5;

    float acc[8];
#pragma unroll
    for (int i = 0; i < 8; i++) acc[i] = 0.f;

    for (int ch = 0; ch < 8; ch++) {
        const int dir = ch >> 2;
        const int jbase = (ch & 3) * 64;
        for (int l = tid; l < 2048; l += 256) {
            int nn = l >> 6, jj = l & 63;
            Ws[nn * 65 + jj] = Wclf[nn * 512 + dir * 256 + jbase + jj];
        }
        const float* hsrc = g_hout + ((size_t)(dir * SEQ + t) * HID + jbase) * 64;
#pragma unroll
        for (int r = 0; r < 4; r++)
            ((float4*)hs)[tid + r * 256] = __ldg(((const float4*)hsrc) + tid + r * 256);
        __syncthreads();
#pragma unroll 16
        for (int jj = 0; jj < 64; jj++) {
            float wv = Ws[n * 65 + jj];
            float4 hA = *(const float4*)&hs[jj * 64 + bg * 8];
            float4 hB = *(const float4*)&hs[jj * 64 + bg * 8 + 4];
            acc[0] += wv * hA.x; acc[1] += wv * hA.y; acc[2] += wv * hA.z; acc[3] += wv * hA.w;
            acc[4] += wv * hB.x; acc[5] += wv * hB.y; acc[6] += wv * hB.z; acc[7] += wv * hB.w;
        }
        __syncthreads();
    }
    const float bias = bclf[n];
#pragma unroll
    for (int bb = 0; bb < 8; bb++) {
        int b = bg * 8 + bb;
        out[((size_t)b * SEQ + t) * NK + n] = acc[bb] + bias;
    }
}

// ---------------- Kernel 4: Viterbi decode (smem-based, no reg arrays) -------
__global__ __launch_bounds__(32) void viterbi_kernel(
    const float* __restrict__ logits, const int* __restrict__ lengths,
    const float* __restrict__ startt, const float* __restrict__ endt,
    const float* __restrict__ trans, float* __restrict__ preds, int write_preds)
{
    __shared__ float transT[32 * 33];     // transT[j][i] = trans[i][j]
    __shared__ float sscore[2][32];
    __shared__ unsigned char hist[511][32];
    const int b = blockIdx.x;
    const int j = threadIdx.x;
    const int len = lengths[b];

#pragma unroll 4
    for (int i = 0; i < 32; i++) transT[j * 33 + i] = trans[i * 32 + j];

    const float* lg = logits + (size_t)b * SEQ * NK;
    float score = startt[j] + lg[j];
    float e_next = lg[NK + j];

    for (int t = 1; t < SEQ; t++) {
        const int buf = t & 1;
        sscore[buf][j] = score;
        __syncwarp();
        float e = e_next;
        if (t + 1 < SEQ) e_next = lg[(t + 1) * NK + j];

        float m0, m1; int a0, a1;
        float bestv = -3.4e38f; int besta = 0;
#pragma unroll
        for (int p = 0; p < 8; p++) {
            float4 s4 = *(const float4*)&sscore[buf][p * 4];
            float v0 = s4.x + transT[j * 33 + p * 4 + 0];
            float v1 = s4.y + transT[j * 33 + p * 4 + 1];
            float v2 = s4.z + transT[j * 33 + p * 4 + 2];
            float v3 = s4.w + transT[j * 33 + p * 4 + 3];
            bool t01 = v1 > v0; m0 = t01 ? v1 : v0; a0 = t01 ? p * 4 + 1 : p * 4;
            bool t23 = v3 > v2; m1 = t23 ? v3 : v2; a1 = t23 ? p * 4 + 3 : p * 4 + 2;
            bool tq = m1 > m0; float mq = tq ? m1 : m0; int aq = tq ? a1 : a0;
            bool tb = mq > bestv;   // p ascending: strict > keeps first max
            bestv = tb ? mq : bestv;
            besta = tb ? aq : besta;
        }
        float nscore = bestv + e;
        bool msk = (t < len);
        hist[t - 1][j] = (unsigned char)(msk ? besta : j);
        score = msk ? nscore : score;
        __syncwarp();
    }
    score += endt[j];

    float bvv = score; int bii = j;
#pragma unroll
    for (int off = 16; off; off >>= 1) {
        float ov = __shfl_xor_sync(0xffffffffu, bvv, off);
        int   oi = __shfl_xor_sync(0xffffffffu, bii, off);
        if (ov > bvv || (ov == bvv && oi < bii)) { bvv = ov; bii = oi; }
    }
    __syncwarp();

    if (write_preds && j == 0) {
        int tag = bii;
        float* pp = preds + (size_t)b * SEQ;
        for (int t = SEQ - 2; t >= 0; t--) {
            pp[t + 1] = (float)(((t + 1) < len) ? tag : 0);
            tag = hist[t][tag];
        }
        pp[0] = (float)((0 < len) ? tag : 0);
    }
}

// ---------------- launch ----------------
extern "C" void kernel_launch(void* const* d_in, const int* in_sizes, int n_in,
                              void* d_out, int out_size)
{
    const float* x     = (const float*)d_in[0];
    const int*   lens  = (const int*)d_in[1];
    const float* Wih_f = (const float*)d_in[3];
    const float* Whh_f = (const float*)d_in[4];
    const float* b_f   = (const float*)d_in[5];
    const float* Wih_b = (const float*)d_in[6];
    const float* Whh_b = (const float*)d_in[7];
    const float* b_b   = (const float*)d_in[8];
    const float* W_clf = (const float*)d_in[9];
    const float* b_clf = (const float*)d_in[10];
    const float* st_t  = (const float*)d_in[11];
    const float* en_t  = (const float*)d_in[12];
    const float* trans = (const float*)d_in[13];
    float* out = (float*)d_out;

    __nv_bfloat16 *xhi, *xlo, *whi, *wlo;
    cudaGetSymbolAddress((void**)&xhi, g_xhi);
    cudaGetSymbolAddress((void**)&xlo, g_xlo);
    cudaGetSymbolAddress((void**)&whi, g_whi);
    cudaGetSymbolAddress((void**)&wlo, g_wlo);

    split_kernel<<<2048, 256>>>(x, xhi, xlo, 32768 * 512);
    split_kernel<<<128, 256>>>(Wih_f, whi, wlo, 1024 * 512);
    split_kernel<<<128, 256>>>(Wih_b, whi + (size_t)1024 * 512, wlo + (size_t)1024 * 512, 1024 * 512);

    gemm_xp_mma_kernel<<<dim3(16, 256), 256>>>(b_f, b_b);

    lstm_kernel<<<128, 256>>>(Whh_f, Whh_b, lens);
    clf_kernel<<<512, 256>>>(W_clf, b_clf, out);

    const int logits_elems = BATCH * SEQ * NK;      // 1048576
    const int preds_elems  = BATCH * SEQ;           // 32768
    int wp = (out_size >= logits_elems + preds_elems) ? 1 : 0;
    viterbi_kernel<<<64, 32>>>(out, lens, st_t, en_t, trans, out + logits_elems, wp);
}